// round 14
// baseline (speedup 1.0000x reference)
#include <cuda_runtime.h>
#include <cuda_bf16.h>

// Problem constants: input shape (N=4, C=3, 128,128,128), fp32.
#define S_SPATIAL    (128 * 128 * 128)           // 2,097,152 elems per (n,c) segment
#define N_BATCH      4
#define C_CHAN       3
#define M_PER_CH     ((long long)N_BATCH * S_SPATIAL)  // 8,388,608 per channel

#define THREADS      512
#define BLK_PER_CH   148                          // 4 segments x 37 ranges
#define RANGES_PER_SEG 37
#define TOTAL_BLOCKS (C_CHAN * BLK_PER_CH)        // 444 = 3 blocks/SM, single wave

#define VEC4_PER_SEG (S_SPATIAL / 4)              // 524,288
#define RANGE_Q      (VEC4_PER_SEG / RANGES_PER_SEG)        // 14,169
#define RANGE_REM    (VEC4_PER_SEG - RANGE_Q * RANGES_PER_SEG)  // 35

#define LOG2_CLAMP   (-144.26950408889634f)       // -100 / ln(2)
#define LN2          0.6931471805599453

// Per-block partials: slot [ch][t] rewritten every launch -> no init kernel,
// deterministic graph replays. Counts kept as float (exact: integers < 2^24).
__device__ float    g_psum[C_CHAN][BLK_PER_CH];
__device__ float    g_pcnt[C_CHAN][BLK_PER_CH];
// Arrival counter; last block resets it to 0 each launch.
__device__ unsigned g_arrive = 0u;

__global__ __launch_bounds__(THREADS, 3) void bce_fused_kernel(
    const float* __restrict__ p_in,
    const float* __restrict__ t_in,
    float* __restrict__ out)
{
    const int b   = blockIdx.x;
    const int ch  = b % C_CHAN;                   // channel, uniform per block
    const int t   = b / C_CHAN;                   // 0..147 within channel
    const int n   = t / RANGES_PER_SEG;           // batch segment 0..3
    const int r   = t % RANGES_PER_SEG;           // range within segment 0..36
    const int tid = threadIdx.x;

    // Contiguous vec4 range [start, start+len) inside segment (n, ch).
    const int start = r * RANGE_Q + (r < RANGE_REM ? r : RANGE_REM);
    const int len   = RANGE_Q + (r < RANGE_REM ? 1 : 0);

    const size_t seg_base = (size_t)(n * C_CHAN + ch) * S_SPATIAL;
    const float4* __restrict__ p4 = (const float4*)(p_in + seg_base) + start;
    const float4* __restrict__ t4 = (const float4*)(t_in + seg_base) + start;

    float sum2 = 0.0f;   // sum of clamped log2 terms
    float tsum = 0.0f;   // positive count (targets are exactly 0.0/1.0)

    #pragma unroll 4
    for (int i = tid; i < len; i += THREADS) {
        float4 pv = p4[i];
        float4 tv = t4[i];
        {
            float x = (tv.x != 0.0f) ? pv.x : (1.0f - pv.x);
            sum2 += fmaxf(__log2f(x), LOG2_CLAMP);
            tsum += tv.x;
        }
        {
            float x = (tv.y != 0.0f) ? pv.y : (1.0f - pv.y);
            sum2 += fmaxf(__log2f(x), LOG2_CLAMP);
            tsum += tv.y;
        }
        {
            float x = (tv.z != 0.0f) ? pv.z : (1.0f - pv.z);
            sum2 += fmaxf(__log2f(x), LOG2_CLAMP);
            tsum += tv.z;
        }
        {
            float x = (tv.w != 0.0f) ? pv.w : (1.0f - pv.w);
            sum2 += fmaxf(__log2f(x), LOG2_CLAMP);
            tsum += tv.w;
        }
    }

    // ---- Warp + block reduction ----
    #pragma unroll
    for (int off = 16; off > 0; off >>= 1) {
        sum2 += __shfl_xor_sync(0xFFFFFFFFu, sum2, off);
        tsum += __shfl_xor_sync(0xFFFFFFFFu, tsum, off);
    }

    __shared__ float s_sum[THREADS / 32];
    __shared__ float s_cnt[THREADS / 32];
    __shared__ bool  s_last;
    const int wid = tid >> 5;
    const int lid = tid & 31;
    if (lid == 0) {
        s_sum[wid] = sum2;
        s_cnt[wid] = tsum;
    }
    __syncthreads();

    if (tid == 0) {
        float bsum = 0.0f;
        float bcnt = 0.0f;
        #pragma unroll
        for (int w = 0; w < THREADS / 32; w++) {
            bsum += s_sum[w];
            bcnt += s_cnt[w];
        }
        g_psum[ch][t] = bsum;
        g_pcnt[ch][t] = bcnt;
        __threadfence();                          // publish partials device-wide
        unsigned prev = atomicAdd(&g_arrive, 1u);
        s_last = (prev == TOTAL_BLOCKS - 1);
    }
    __syncthreads();

    if (!s_last) return;

    // ---- Last block: fp32 tail over 3 x 148 partials ----
    float fs0 = 0.f, fs1 = 0.f, fs2 = 0.f;
    float fc0 = 0.f, fc1 = 0.f, fc2 = 0.f;
    if (tid < BLK_PER_CH) {
        fs0 = g_psum[0][tid]; fc0 = g_pcnt[0][tid];
        fs1 = g_psum[1][tid]; fc1 = g_pcnt[1][tid];
        fs2 = g_psum[2][tid]; fc2 = g_pcnt[2][tid];
    }

    #pragma unroll
    for (int off = 16; off > 0; off >>= 1) {
        fs0 += __shfl_xor_sync(0xFFFFFFFFu, fs0, off);
        fs1 += __shfl_xor_sync(0xFFFFFFFFu, fs1, off);
        fs2 += __shfl_xor_sync(0xFFFFFFFFu, fs2, off);
        fc0 += __shfl_xor_sync(0xFFFFFFFFu, fc0, off);
        fc1 += __shfl_xor_sync(0xFFFFFFFFu, fc1, off);
        fc2 += __shfl_xor_sync(0xFFFFFFFFu, fc2, off);
    }

    __shared__ float f_sum[C_CHAN][THREADS / 32];
    __shared__ float f_cnt[C_CHAN][THREADS / 32];
    if (lid == 0) {
        f_sum[0][wid] = fs0; f_sum[1][wid] = fs1; f_sum[2][wid] = fs2;
        f_cnt[0][wid] = fc0; f_cnt[1][wid] = fc1; f_cnt[2][wid] = fc2;
    }
    __syncthreads();

    if (tid == 0) {
        double total = 0.0;
        #pragma unroll
        for (int c = 0; c < C_CHAN; c++) {
            float s = 0.0f;
            float ones = 0.0f;
            #pragma unroll
            for (int w = 0; w < THREADS / 32; w++) {
                s    += f_sum[c][w];
                ones += f_cnt[c][w];
            }
            double bce = -((double)s * LN2) / (double)M_PER_CH;   // log2 -> ln, channel mean
            double wgt = (ones > 0.0f) ? ((double)M_PER_CH / (double)ones)
                                       : 1000.0;                  // EMPTY_WEIGHT
            total += wgt * bce;
        }
        out[0] = (float)(total / (double)C_CHAN);
        g_arrive = 0u;                                            // self-reset for next replay
    }
}

extern "C" void kernel_launch(void* const* d_in, const int* in_sizes, int n_in,
                              void* d_out, int out_size) {
    const float* input  = (const float*)d_in[0];
    const float* target = (const float*)d_in[1];
    float* out = (float*)d_out;

    bce_fused_kernel<<<TOTAL_BLOCKS, THREADS>>>(input, target, out);
}

// round 15
// speedup vs baseline: 1.0544x; 1.0544x over previous
#include <cuda_runtime.h>
#include <cuda_bf16.h>

// Problem constants: input shape (N=4, C=3, 128,128,128), fp32.
#define S_SPATIAL (128 * 128 * 128)          // 2,097,152 contiguous elems per (n,c) segment
#define N_BATCH   4
#define C_CHAN    3
#define N_SEG     (N_BATCH * C_CHAN)          // 12 contiguous segments
#define M_PER_CH  ((long long)N_BATCH * S_SPATIAL)   // 8,388,608 elems per channel

#define BLOCKS_PER_SEG 64
#define THREADS        256
#define SLOTS_PER_CH   (N_BATCH * BLOCKS_PER_SEG)    // 256 partial slots per channel
#define TOTAL_BLOCKS   (N_SEG * BLOCKS_PER_SEG)      // 768
#define ELEMS_PER_BLK  (S_SPATIAL / BLOCKS_PER_SEG)  // 32768
#define VEC4_PER_BLK   (ELEMS_PER_BLK / 4)           // 8192 (compile-time trip count)

// Per-block partials, channel-major: slot = c * 256 + (n * 64 + chunk).
// Every slot is overwritten on every launch -> no init kernel, no atomics,
// no fences. The kernel boundary orders the writes for the final kernel.
__device__ float g_psum[C_CHAN * SLOTS_PER_CH];
__device__ int   g_pcnt[C_CHAN * SLOTS_PER_CH];

// ---- Kernel 1: streaming BCE partial reduction (best measured mainloop) ----
__global__ __launch_bounds__(THREADS) void bce_reduce_kernel(
    const float* __restrict__ p_in,
    const float* __restrict__ t_in)
{
    const int seg   = blockIdx.x >> 6;        // blockIdx.x / 64
    const int chunk = blockIdx.x & 63;
    const int c     = seg % C_CHAN;           // channel is uniform per block
    const int n     = seg / C_CHAN;           // batch index

    const size_t base = (size_t)seg * S_SPATIAL + (size_t)chunk * ELEMS_PER_BLK;
    const float4* __restrict__ p4 = (const float4*)(p_in + base);
    const float4* __restrict__ t4 = (const float4*)(t_in + base);

    float sum = 0.0f;
    int   cnt = 0;

    #pragma unroll 4
    for (int i = threadIdx.x; i < VEC4_PER_BLK; i += THREADS) {
        float4 pv = p4[i];
        float4 tv = t4[i];

        {
            bool one = (tv.x != 0.0f);
            float x = one ? pv.x : (1.0f - pv.x);
            sum += fmaxf(__logf(x), -100.0f);
            cnt += one;
        }
        {
            bool one = (tv.y != 0.0f);
            float x = one ? pv.y : (1.0f - pv.y);
            sum += fmaxf(__logf(x), -100.0f);
            cnt += one;
        }
        {
            bool one = (tv.z != 0.0f);
            float x = one ? pv.z : (1.0f - pv.z);
            sum += fmaxf(__logf(x), -100.0f);
            cnt += one;
        }
        {
            bool one = (tv.w != 0.0f);
            float x = one ? pv.w : (1.0f - pv.w);
            sum += fmaxf(__logf(x), -100.0f);
            cnt += one;
        }
    }

    // Warp reduction
    #pragma unroll
    for (int off = 16; off > 0; off >>= 1) {
        sum += __shfl_xor_sync(0xFFFFFFFFu, sum, off);
        cnt += __shfl_xor_sync(0xFFFFFFFFu, cnt, off);
    }

    // Block reduction across 8 warps
    __shared__ float s_sum[THREADS / 32];
    __shared__ int   s_cnt[THREADS / 32];
    const int wid = threadIdx.x >> 5;
    const int lid = threadIdx.x & 31;
    if (lid == 0) {
        s_sum[wid] = sum;
        s_cnt[wid] = cnt;
    }
    __syncthreads();

    if (threadIdx.x == 0) {
        float bsum = 0.0f;
        int   bcnt = 0;
        #pragma unroll
        for (int w = 0; w < THREADS / 32; w++) {
            bsum += s_sum[w];
            bcnt += s_cnt[w];
        }
        const int slot = c * SLOTS_PER_CH + n * BLOCKS_PER_SEG + chunk;
        g_psum[slot] = bsum;      // plain store; no fence, no atomic
        g_pcnt[slot] = bcnt;
    }
}

// ---- Kernel 2: cheap fp32/int finalize (3 channels x 256 slots) ----
// fp32 pairwise tree over 256 block-partials: rel error ~5e-7 << 1e-3.
__global__ __launch_bounds__(THREADS) void bce_final_kernel(float* __restrict__ out)
{
    const int tid = threadIdx.x;              // 0..255, one slot per channel
    const int wid = tid >> 5;
    const int lid = tid & 31;

    float fs0 = g_psum[0 * SLOTS_PER_CH + tid];
    float fs1 = g_psum[1 * SLOTS_PER_CH + tid];
    float fs2 = g_psum[2 * SLOTS_PER_CH + tid];
    int   ic0 = g_pcnt[0 * SLOTS_PER_CH + tid];
    int   ic1 = g_pcnt[1 * SLOTS_PER_CH + tid];
    int   ic2 = g_pcnt[2 * SLOTS_PER_CH + tid];

    #pragma unroll
    for (int off = 16; off > 0; off >>= 1) {
        fs0 += __shfl_xor_sync(0xFFFFFFFFu, fs0, off);
        fs1 += __shfl_xor_sync(0xFFFFFFFFu, fs1, off);
        fs2 += __shfl_xor_sync(0xFFFFFFFFu, fs2, off);
        ic0 += __shfl_xor_sync(0xFFFFFFFFu, ic0, off);
        ic1 += __shfl_xor_sync(0xFFFFFFFFu, ic1, off);
        ic2 += __shfl_xor_sync(0xFFFFFFFFu, ic2, off);
    }

    __shared__ float f_sum[C_CHAN][THREADS / 32];
    __shared__ int   f_cnt[C_CHAN][THREADS / 32];
    if (lid == 0) {
        f_sum[0][wid] = fs0; f_sum[1][wid] = fs1; f_sum[2][wid] = fs2;
        f_cnt[0][wid] = ic0; f_cnt[1][wid] = ic1; f_cnt[2][wid] = ic2;
    }
    __syncthreads();

    if (tid == 0) {
        double total = 0.0;
        #pragma unroll
        for (int ch = 0; ch < C_CHAN; ch++) {
            float s = 0.0f;
            int   ones = 0;
            #pragma unroll
            for (int w = 0; w < THREADS / 32; w++) {
                s    += f_sum[ch][w];
                ones += f_cnt[ch][w];
            }
            double bce = -(double)s / (double)M_PER_CH;         // channel mean, negated
            double wgt = (ones > 0) ? ((double)M_PER_CH / (double)ones)
                                    : 1000.0;                   // EMPTY_WEIGHT
            total += wgt * bce;
        }
        out[0] = (float)(total / (double)C_CHAN);
    }
}

extern "C" void kernel_launch(void* const* d_in, const int* in_sizes, int n_in,
                              void* d_out, int out_size) {
    const float* input  = (const float*)d_in[0];
    const float* target = (const float*)d_in[1];
    float* out = (float*)d_out;

    bce_reduce_kernel<<<TOTAL_BLOCKS, THREADS>>>(input, target);
    bce_final_kernel<<<1, THREADS>>>(out);
}

// round 16
// speedup vs baseline: 1.0616x; 1.0068x over previous
#include <cuda_runtime.h>
#include <cuda_bf16.h>

// Problem constants: input shape (N=4, C=3, 128,128,128), fp32.
#define S_SPATIAL (128 * 128 * 128)          // 2,097,152 contiguous elems per (n,c) segment
#define N_BATCH   4
#define C_CHAN    3
#define N_SEG     (N_BATCH * C_CHAN)          // 12 contiguous segments
#define M_PER_CH  ((long long)N_BATCH * S_SPATIAL)   // 8,388,608 elems per channel

#define BLOCKS_PER_SEG 64
#define THREADS        256
#define SLOTS_PER_CH   (N_BATCH * BLOCKS_PER_SEG)    // 256 partial slots per channel
#define TOTAL_BLOCKS   (N_SEG * BLOCKS_PER_SEG)      // 768
#define ELEMS_PER_BLK  (S_SPATIAL / BLOCKS_PER_SEG)  // 32768
#define VEC4_PER_BLK   (ELEMS_PER_BLK / 4)           // 8192 (compile-time trip count)

// Per-block partials, channel-major: slot = c * 256 + (n * 64 + chunk).
// Every slot rewritten every launch -> no init kernel, deterministic replays.
__device__ float    g_psum[C_CHAN * SLOTS_PER_CH];
__device__ int      g_pcnt[C_CHAN * SLOTS_PER_CH];
// Arrival counter; last block resets it to 0 each launch.
__device__ unsigned g_arrive = 0u;

__global__ __launch_bounds__(THREADS) void bce_fused_kernel(
    const float* __restrict__ p_in,
    const float* __restrict__ t_in,
    float* __restrict__ out)
{
    const int seg   = blockIdx.x >> 6;        // 0..11
    const int chunk = blockIdx.x & 63;
    const int c     = seg % C_CHAN;           // channel, uniform per block
    const int n     = seg / C_CHAN;           // batch index

    const size_t base = (size_t)seg * S_SPATIAL + (size_t)chunk * ELEMS_PER_BLK;
    const float4* __restrict__ p4 = (const float4*)(p_in + base);
    const float4* __restrict__ t4 = (const float4*)(t_in + base);

    float sum = 0.0f;
    int   cnt = 0;

    // Round-8 mainloop, byte-identical (measured ~30.7us standalone).
    #pragma unroll 4
    for (int i = threadIdx.x; i < VEC4_PER_BLK; i += THREADS) {
        float4 pv = p4[i];
        float4 tv = t4[i];
        {
            bool one = (tv.x != 0.0f);
            float x = one ? pv.x : (1.0f - pv.x);
            sum += fmaxf(__logf(x), -100.0f);
            cnt += one;
        }
        {
            bool one = (tv.y != 0.0f);
            float x = one ? pv.y : (1.0f - pv.y);
            sum += fmaxf(__logf(x), -100.0f);
            cnt += one;
        }
        {
            bool one = (tv.z != 0.0f);
            float x = one ? pv.z : (1.0f - pv.z);
            sum += fmaxf(__logf(x), -100.0f);
            cnt += one;
        }
        {
            bool one = (tv.w != 0.0f);
            float x = one ? pv.w : (1.0f - pv.w);
            sum += fmaxf(__logf(x), -100.0f);
            cnt += one;
        }
    }

    // Warp reduction
    #pragma unroll
    for (int off = 16; off > 0; off >>= 1) {
        sum += __shfl_xor_sync(0xFFFFFFFFu, sum, off);
        cnt += __shfl_xor_sync(0xFFFFFFFFu, cnt, off);
    }

    // Block reduction across 8 warps
    __shared__ float s_sum[THREADS / 32];
    __shared__ int   s_cnt[THREADS / 32];
    __shared__ bool  s_last;
    const int wid = threadIdx.x >> 5;
    const int lid = threadIdx.x & 31;
    if (lid == 0) {
        s_sum[wid] = sum;
        s_cnt[wid] = cnt;
    }
    __syncthreads();

    if (threadIdx.x == 0) {
        float bsum = 0.0f;
        int   bcnt = 0;
        #pragma unroll
        for (int w = 0; w < THREADS / 32; w++) {
            bsum += s_sum[w];
            bcnt += s_cnt[w];
        }
        const int slot = c * SLOTS_PER_CH + n * BLOCKS_PER_SEG + chunk;
        g_psum[slot] = bsum;      // st.global: write-through to L2
        g_pcnt[slot] = bcnt;

        // acq_rel RMW: release makes the partial stores above visible before
        // the increment; acquire orders the last block's partial reads after
        // it. NO __threadfence() -> no CCTL.IVALL L1 flush, no MEMBAR drain.
        unsigned prev;
        asm volatile("atom.add.acq_rel.gpu.global.u32 %0, [%1], %2;"
                     : "=r"(prev)
                     : "l"(&g_arrive), "r"(1u)
                     : "memory");
        s_last = (prev == TOTAL_BLOCKS - 1);
    }
    __syncthreads();

    if (!s_last) return;

    // ---- Last block: fp32/int tail over 3 x 256 partials ----
    // __ldcg = L2-direct loads (fresh data; dodge any stale self-written L1 line).
    const int tid = threadIdx.x;
    float fs0 = __ldcg(&g_psum[0 * SLOTS_PER_CH + tid]);
    float fs1 = __ldcg(&g_psum[1 * SLOTS_PER_CH + tid]);
    float fs2 = __ldcg(&g_psum[2 * SLOTS_PER_CH + tid]);
    int   ic0 = __ldcg(&g_pcnt[0 * SLOTS_PER_CH + tid]);
    int   ic1 = __ldcg(&g_pcnt[1 * SLOTS_PER_CH + tid]);
    int   ic2 = __ldcg(&g_pcnt[2 * SLOTS_PER_CH + tid]);

    #pragma unroll
    for (int off = 16; off > 0; off >>= 1) {
        fs0 += __shfl_xor_sync(0xFFFFFFFFu, fs0, off);
        fs1 += __shfl_xor_sync(0xFFFFFFFFu, fs1, off);
        fs2 += __shfl_xor_sync(0xFFFFFFFFu, fs2, off);
        ic0 += __shfl_xor_sync(0xFFFFFFFFu, ic0, off);
        ic1 += __shfl_xor_sync(0xFFFFFFFFu, ic1, off);
        ic2 += __shfl_xor_sync(0xFFFFFFFFu, ic2, off);
    }

    __shared__ float f_sum[C_CHAN][THREADS / 32];
    __shared__ int   f_cnt[C_CHAN][THREADS / 32];
    if (lid == 0) {
        f_sum[0][wid] = fs0; f_sum[1][wid] = fs1; f_sum[2][wid] = fs2;
        f_cnt[0][wid] = ic0; f_cnt[1][wid] = ic1; f_cnt[2][wid] = ic2;
    }
    __syncthreads();

    if (tid == 0) {
        double total = 0.0;
        #pragma unroll
        for (int ch = 0; ch < C_CHAN; ch++) {
            float s = 0.0f;
            int   ones = 0;
            #pragma unroll
            for (int w = 0; w < THREADS / 32; w++) {
                s    += f_sum[ch][w];
                ones += f_cnt[ch][w];
            }
            double bce = -(double)s / (double)M_PER_CH;        // channel mean, negated
            double wgt = (ones > 0) ? ((double)M_PER_CH / (double)ones)
                                    : 1000.0;                  // EMPTY_WEIGHT
            total += wgt * bce;
        }
        out[0] = (float)(total / (double)C_CHAN);
        g_arrive = 0u;                                         // self-reset for next replay
    }
}

extern "C" void kernel_launch(void* const* d_in, const int* in_sizes, int n_in,
                              void* d_out, int out_size) {
    const float* input  = (const float*)d_in[0];
    const float* target = (const float*)d_in[1];
    float* out = (float*)d_out;

    bce_fused_kernel<<<TOTAL_BLOCKS, THREADS>>>(input, target, out);
}

// round 17
// speedup vs baseline: 1.0626x; 1.0009x over previous
#include <cuda_runtime.h>
#include <cuda_bf16.h>
#include <cstdint>

// Problem constants: input shape (N=4, C=3, 128,128,128), fp32.
#define S_SPATIAL    (128 * 128 * 128)            // 2,097,152 elems per (n,c) segment
#define C_CHAN       3
#define M_PER_CH     ((long long)4 * S_SPATIAL)   // 8,388,608 elems per channel

#define THREADS      256
#define BLK_PER_CH   148
#define TOTAL_BLOCKS (C_CHAN * BLK_PER_CH)        // 444 = 3 blocks/SM, single wave

// TMA tiling: 8 KB per array per tile, double buffered.
#define TILE_V4       512                          // 512 float4 = 2048 elems = 8 KB
#define TILE_ELEMS    (TILE_V4 * 4)                // 2048
#define TILE_BYTES    (TILE_V4 * 16)               // 8192
#define V4_PER_SEG    (S_SPATIAL / 4)              // 524,288
#define TILES_PER_SEG (V4_PER_SEG / TILE_V4)       // 1024
#define TILES_PER_CH  (4 * TILES_PER_SEG)          // 4096

// Per-block partials; every slot rewritten every launch -> no init kernel.
__device__ float    g_psum[C_CHAN][BLK_PER_CH];
__device__ int      g_pcnt[C_CHAN][BLK_PER_CH];
// Arrival counter; last block resets it each launch (deterministic replays).
__device__ unsigned g_arrive = 0u;

static __device__ __forceinline__ uint32_t smem_u32(const void* p) {
    uint32_t a;
    asm("{ .reg .u64 t; cvta.to.shared.u64 t, %1; cvt.u32.u64 %0, t; }"
        : "=r"(a) : "l"(p));
    return a;
}

static __device__ __forceinline__ void mbar_init(uint32_t mb, uint32_t count) {
    asm volatile("mbarrier.init.shared.b64 [%0], %1;" :: "r"(mb), "r"(count) : "memory");
}

static __device__ __forceinline__ void mbar_expect_tx(uint32_t mb, uint32_t bytes) {
    asm volatile("mbarrier.arrive.expect_tx.shared.b64 _, [%0], %1;"
                 :: "r"(mb), "r"(bytes) : "memory");
}

static __device__ __forceinline__ void bulk_g2s(uint32_t dst_smem, const void* src_gmem,
                                                uint32_t bytes, uint32_t mb) {
    asm volatile("cp.async.bulk.shared::cluster.global.mbarrier::complete_tx::bytes "
                 "[%0], [%1], %2, [%3];"
                 :: "r"(dst_smem), "l"(src_gmem), "r"(bytes), "r"(mb) : "memory");
}

static __device__ __forceinline__ void mbar_wait(uint32_t mb, uint32_t parity) {
    uint32_t done;
    asm volatile(
        "{\n\t"
        ".reg .pred p;\n\t"
        "mbarrier.try_wait.parity.acquire.cta.shared::cta.b64 p, [%1], %2;\n\t"
        "selp.b32 %0, 1, 0, p;\n\t"
        "}"
        : "=r"(done) : "r"(mb), "r"(parity) : "memory");
    if (!done) {
        asm volatile(
            "{\n\t"
            ".reg .pred P1;\n\t"
            "WAIT_LOOP_%=:\n\t"
            "mbarrier.try_wait.parity.acquire.cta.shared::cta.b64 P1, [%0], %1, 0x989680;\n\t"
            "@P1 bra.uni WAIT_DONE_%=;\n\t"
            "bra.uni WAIT_LOOP_%=;\n\t"
            "WAIT_DONE_%=:\n\t"
            "}"
            :: "r"(mb), "r"(parity) : "memory");
    }
}

__global__ __launch_bounds__(THREADS) void bce_tma_kernel(
    const float* __restrict__ p_in,
    const float* __restrict__ t_in,
    float* __restrict__ out)
{
    __shared__ __align__(16) float4 p_buf[2][TILE_V4];   // 2 x 8 KB
    __shared__ __align__(16) float4 t_buf[2][TILE_V4];   // 2 x 8 KB
    __shared__ __align__(8)  unsigned long long mbar[2];

    const int b   = blockIdx.x;
    const int ch  = b % C_CHAN;                  // channel, uniform per block
    const int t   = b / C_CHAN;                  // 0..147 within channel
    const int tid = threadIdx.x;

    // This block's tile count: tiles j = t + i*148, j < 4096  ->  L = 28 or 27.
    const int L = (TILES_PER_CH - t + BLK_PER_CH - 1) / BLK_PER_CH;

    const uint32_t mb0 = smem_u32(&mbar[0]);
    const uint32_t mb1 = smem_u32(&mbar[1]);
    const uint32_t pb0 = smem_u32(&p_buf[0][0]);
    const uint32_t pb1 = smem_u32(&p_buf[1][0]);
    const uint32_t tb0 = smem_u32(&t_buf[0][0]);
    const uint32_t tb1 = smem_u32(&t_buf[1][0]);

    if (tid == 0) {
        mbar_init(mb0, 1);
        mbar_init(mb1, 1);
        asm volatile("fence.proxy.async;" ::: "memory");
    }
    __syncthreads();

    // Issue tile i into stage (i&1).
    auto issue = [&](int i) {
        const int j   = t + i * BLK_PER_CH;      // global tile index in channel
        const int s   = i & 1;
        const int n   = j >> 10;                 // segment (1024 tiles/segment)
        const int pos = j & 1023;
        const size_t base_e = (size_t)(n * C_CHAN + ch) * S_SPATIAL
                            + (size_t)pos * TILE_ELEMS;
        const uint32_t mb = s ? mb1 : mb0;
        mbar_expect_tx(mb, 2 * TILE_BYTES);
        bulk_g2s(s ? pb1 : pb0, p_in + base_e, TILE_BYTES, mb);
        bulk_g2s(s ? tb1 : tb0, t_in + base_e, TILE_BYTES, mb);
    };

    float sum = 0.0f;
    int   cnt = 0;

    if (tid == 0) {
        issue(0);
        if (L > 1) issue(1);
    }

    for (int i = 0; i < L; i++) {
        const int s = i & 1;
        mbar_wait(s ? mb1 : mb0, (i >> 1) & 1);

        // Compute: 2 float4 per array per thread (compile-time bounds).
        #pragma unroll
        for (int u = 0; u < 2; u++) {
            float4 pv = p_buf[s][tid + u * THREADS];
            float4 tv = t_buf[s][tid + u * THREADS];
            {
                bool one = (tv.x != 0.0f);
                float x = one ? pv.x : (1.0f - pv.x);
                sum += fmaxf(__logf(x), -100.0f);
                cnt += one;
            }
            {
                bool one = (tv.y != 0.0f);
                float x = one ? pv.y : (1.0f - pv.y);
                sum += fmaxf(__logf(x), -100.0f);
                cnt += one;
            }
            {
                bool one = (tv.z != 0.0f);
                float x = one ? pv.z : (1.0f - pv.z);
                sum += fmaxf(__logf(x), -100.0f);
                cnt += one;
            }
            {
                bool one = (tv.w != 0.0f);
                float x = one ? pv.w : (1.0f - pv.w);
                sum += fmaxf(__logf(x), -100.0f);
                cnt += one;
            }
        }

        __syncthreads();                         // all reads of stage s done
        if (tid == 0 && i + 2 < L) issue(i + 2); // refill stage s
    }

    // ---- Warp + block reduction ----
    #pragma unroll
    for (int off = 16; off > 0; off >>= 1) {
        sum += __shfl_xor_sync(0xFFFFFFFFu, sum, off);
        cnt += __shfl_xor_sync(0xFFFFFFFFu, cnt, off);
    }

    __shared__ float s_sum[THREADS / 32];
    __shared__ int   s_cnt[THREADS / 32];
    __shared__ bool  s_last;
    const int wid = tid >> 5;
    const int lid = tid & 31;
    if (lid == 0) {
        s_sum[wid] = sum;
        s_cnt[wid] = cnt;
    }
    __syncthreads();

    if (tid == 0) {
        float bsum = 0.0f;
        int   bcnt = 0;
        #pragma unroll
        for (int w = 0; w < THREADS / 32; w++) {
            bsum += s_sum[w];
            bcnt += s_cnt[w];
        }
        g_psum[ch][t] = bsum;
        g_pcnt[ch][t] = bcnt;
        // acq_rel RMW orders the partial stores above (release) and the last
        // block's partial reads below (acquire). Proven in R16.
        unsigned prev;
        asm volatile("atom.add.acq_rel.gpu.global.u32 %0, [%1], %2;"
                     : "=r"(prev) : "l"(&g_arrive), "r"(1u) : "memory");
        s_last = (prev == TOTAL_BLOCKS - 1);
    }
    __syncthreads();

    if (!s_last) return;

    // ---- Last block: fp32/int tail over 3 x 148 partials ----
    float fs0 = 0.f, fs1 = 0.f, fs2 = 0.f;
    int   ic0 = 0,   ic1 = 0,   ic2 = 0;
    if (tid < BLK_PER_CH) {
        fs0 = __ldcg(&g_psum[0][tid]); ic0 = __ldcg(&g_pcnt[0][tid]);
        fs1 = __ldcg(&g_psum[1][tid]); ic1 = __ldcg(&g_pcnt[1][tid]);
        fs2 = __ldcg(&g_psum[2][tid]); ic2 = __ldcg(&g_pcnt[2][tid]);
    }

    #pragma unroll
    for (int off = 16; off > 0; off >>= 1) {
        fs0 += __shfl_xor_sync(0xFFFFFFFFu, fs0, off);
        fs1 += __shfl_xor_sync(0xFFFFFFFFu, fs1, off);
        fs2 += __shfl_xor_sync(0xFFFFFFFFu, fs2, off);
        ic0 += __shfl_xor_sync(0xFFFFFFFFu, ic0, off);
        ic1 += __shfl_xor_sync(0xFFFFFFFFu, ic1, off);
        ic2 += __shfl_xor_sync(0xFFFFFFFFu, ic2, off);
    }

    __shared__ float f_sum[C_CHAN][THREADS / 32];
    __shared__ int   f_cnt[C_CHAN][THREADS / 32];
    if (lid == 0) {
        f_sum[0][wid] = fs0; f_sum[1][wid] = fs1; f_sum[2][wid] = fs2;
        f_cnt[0][wid] = ic0; f_cnt[1][wid] = ic1; f_cnt[2][wid] = ic2;
    }
    __syncthreads();

    if (tid == 0) {
        double total = 0.0;
        #pragma unroll
        for (int c = 0; c < C_CHAN; c++) {
            float s = 0.0f;
            int   ones = 0;
            #pragma unroll
            for (int w = 0; w < THREADS / 32; w++) {
                s    += f_sum[c][w];
                ones += f_cnt[c][w];
            }
            double bce = -(double)s / (double)M_PER_CH;        // channel mean, negated
            double wgt = (ones > 0) ? ((double)M_PER_CH / (double)ones)
                                    : 1000.0;                  // EMPTY_WEIGHT
            total += wgt * bce;
        }
        out[0] = (float)(total / (double)C_CHAN);
        g_arrive = 0u;                                         // self-reset for next replay
    }
}

extern "C" void kernel_launch(void* const* d_in, const int* in_sizes, int n_in,
                              void* d_out, int out_size) {
    const float* input  = (const float*)d_in[0];
    const float* target = (const float*)d_in[1];
    float* out = (float*)d_out;

    bce_tma_kernel<<<TOTAL_BLOCKS, THREADS>>>(input, target, out);
}